// round 3
// baseline (speedup 1.0000x reference)
#include <cuda_runtime.h>
#include <cstdint>

// Quincunx lattice max pooling (row-pair + shuffle-edge variant).
// Inputs: coset0, coset1 each [B=4, C=32, H=512, W=512] f32.
// Output: [2, B, C, H, W] f32.
//
// out0[i,j] = max(c0[i,j], c0[i+1,j], c0[i,j+1], c0[i+1,j+1], c1[i,j])
// out1[i,j] = max(c1[i,j], c1[i+1,j], c1[i,j+1], c1[i+1,j+1], c0[i+1,j+1])
// Out-of-range -> -inf.
//
// Each thread handles a float4 column at rows (2r, 2r+1): loads 3 row-vectors
// per coset, writes 2 row-vectors per output coset. The j+4 edge element is
// lane+1's .x via warp shuffle; only lane 31 falls back to a scalar load.

#define NEG_INF __int_as_float(0xff800000)

__device__ __forceinline__ float fmax5(float a, float b, float c, float d, float e) {
    return fmaxf(fmaxf(fmaxf(a, b), fmaxf(c, d)), e);
}

// planes = B*C = 128, H = 512 (256 row pairs), W4 = 128.
// total threads = 128 * 256 * 128 = 4194304.
__global__ void __launch_bounds__(256) lattice_pool_kernel(
    const float4* __restrict__ c0,
    const float4* __restrict__ c1,
    float4* __restrict__ out0,
    float4* __restrict__ out1)
{
    const unsigned idx = blockIdx.x * blockDim.x + threadIdx.x;
    const unsigned jv = idx & 127;            // float4 column
    const unsigned r  = (idx >> 7) & 255;     // row pair (rows 2r, 2r+1)

    // vec index of (plane, row 2r, jv):  pos = p*65536 + 2r*128 + jv = 2*idx - jv
    const unsigned pos = 2u * idx - jv;

    const bool hasR2  = (r < 255);            // row 2r+2 exists
    const bool hasCol = (jv < 127);

    const unsigned posR2 = hasR2 ? pos + 256u : pos;

    // Rows 2r, 2r+1, 2r+2 of both cosets (row 2r+1 always in range).
    float4 a0 = c0[pos];
    float4 a1 = c0[pos + 128u];
    float4 b0 = c1[pos];
    float4 b1 = c1[pos + 128u];
    float4 a2 = c0[posR2];
    float4 b2 = c1[posR2];
    if (!hasR2) {
        a2 = make_float4(NEG_INF, NEG_INF, NEG_INF, NEG_INF);
        b2 = make_float4(NEG_INF, NEG_INF, NEG_INF, NEG_INF);
    }

    // j+4 edge elements: lane+1's .x. Warp lanes cover 32 consecutive jv in
    // the same row, so only lane 31 crosses a warp boundary.
    float a0e = __shfl_down_sync(0xffffffffu, a0.x, 1);
    float a1e = __shfl_down_sync(0xffffffffu, a1.x, 1);
    float a2e = __shfl_down_sync(0xffffffffu, a2.x, 1);
    float b0e = __shfl_down_sync(0xffffffffu, b0.x, 1);
    float b1e = __shfl_down_sync(0xffffffffu, b1.x, 1);
    float b2e = __shfl_down_sync(0xffffffffu, b2.x, 1);

    if ((threadIdx.x & 31u) == 31u) {
        const float* c0f = (const float*)c0;
        const float* c1f = (const float*)c1;
        const unsigned f = (pos + 1u) << 2;   // float index of element j+4, row 2r
        a0e = hasCol ? c0f[f]        : NEG_INF;
        a1e = hasCol ? c0f[f + 512u] : NEG_INF;
        b0e = hasCol ? c1f[f]        : NEG_INF;
        b1e = hasCol ? c1f[f + 512u] : NEG_INF;
        a2e = (hasCol && hasR2) ? c0f[f + 1024u] : NEG_INF;
        b2e = (hasCol && hasR2) ? c1f[f + 1024u] : NEG_INF;
    }

    float4 o;
    // out0 row 2r: own rows a0,a1; cross b0.
    o.x = fmax5(a0.x, a0.y, a1.x, a1.y, b0.x);
    o.y = fmax5(a0.y, a0.z, a1.y, a1.z, b0.y);
    o.z = fmax5(a0.z, a0.w, a1.z, a1.w, b0.z);
    o.w = fmax5(a0.w, a0e,  a1.w, a1e,  b0.w);
    out0[pos] = o;

    // out0 row 2r+1: own rows a1,a2; cross b1.
    o.x = fmax5(a1.x, a1.y, a2.x, a2.y, b1.x);
    o.y = fmax5(a1.y, a1.z, a2.y, a2.z, b1.y);
    o.z = fmax5(a1.z, a1.w, a2.z, a2.w, b1.z);
    o.w = fmax5(a1.w, a1e,  a2.w, a2e,  b1.w);
    out0[pos + 128u] = o;

    // out1 row 2r: own rows b0,b1; cross a1 shifted by (1,1).
    o.x = fmax5(b0.x, b0.y, b1.x, b1.y, a1.y);
    o.y = fmax5(b0.y, b0.z, b1.y, b1.z, a1.z);
    o.z = fmax5(b0.z, b0.w, b1.z, b1.w, a1.w);
    o.w = fmax5(b0.w, b0e,  b1.w, b1e,  a1e);
    out1[pos] = o;

    // out1 row 2r+1: own rows b1,b2; cross a2 shifted by (1,1).
    o.x = fmax5(b1.x, b1.y, b2.x, b2.y, a2.y);
    o.y = fmax5(b1.y, b1.z, b2.y, b2.z, a2.z);
    o.z = fmax5(b1.z, b1.w, b2.z, b2.w, a2.w);
    o.w = fmax5(b1.w, b1e,  b2.w, b2e,  a2e);
    out1[pos + 128u] = o;
}

extern "C" void kernel_launch(void* const* d_in, const int* in_sizes, int n_in,
                              void* d_out, int out_size) {
    const float4* c0 = (const float4*)d_in[0];
    const float4* c1 = (const float4*)d_in[1];
    float4* out0 = (float4*)d_out;
    float4* out1 = out0 + 8388608;  // B*C*H*W floats / 4

    const int total = 4194304;      // 128 planes * 256 row pairs * 128 cols
    const int threads = 256;
    const int blocks = total / threads;  // 16384
    lattice_pool_kernel<<<blocks, threads>>>(c0, c1, out0, out1);
}

// round 4
// speedup vs baseline: 1.0044x; 1.0044x over previous
#include <cuda_runtime.h>
#include <cstdint>

// Quincunx lattice max pooling — memory-roofline version.
// Inputs: coset0, coset1 each [B=4, C=32, H=512, W=512] f32.
// Output: [2, B, C, H, W] f32 (out0 stacked before out1).
//
// out0[i,j] = max(c0[i,j], c0[i+1,j], c0[i,j+1], c0[i+1,j+1], c1[i,j])
// out1[i,j] = max(c1[i,j], c1[i+1,j], c1[i,j+1], c1[i+1,j+1], c0[i+1,j+1])
// Out-of-range -> -inf.
//
// One float4 per thread per output coset. Outputs use streaming stores
// (__stcs, evict-first): they are never re-read, so they shouldn't compete
// with the row-i+1 input reuse in L2.

#define NEG_INF __int_as_float(0xff800000)

__device__ __forceinline__ float fmax5(float a, float b, float c, float d, float e) {
    return fmaxf(fmaxf(fmaxf(a, b), fmaxf(c, d)), e);
}

// H = W = 512, W4 = 128 (float4 lanes per row), planes = B*C = 128.
__global__ void __launch_bounds__(256) lattice_pool_kernel(
    const float4* __restrict__ c0,
    const float4* __restrict__ c1,
    float4* __restrict__ out0,
    float4* __restrict__ out1)
{
    const int idx = blockIdx.x * blockDim.x + threadIdx.x;
    const int jv = idx & 127;          // float4 column
    const int i  = (idx >> 7) & 511;   // row

    const size_t pos = (size_t)idx;    // fully linear layout

    const bool hasRow = (i < 511);
    const bool hasCol = (jv < 127);

    // Row i+1 loads: clamp offset instead of predicating the load, so both
    // LDG.128 pairs issue unconditionally (front-batched).
    const size_t posR = hasRow ? pos + 128 : pos;

    float4 a0 = c0[pos];
    float4 b0 = c1[pos];
    float4 a1 = c0[posR];
    float4 b1 = c1[posR];
    if (!hasRow) {
        a1 = make_float4(NEG_INF, NEG_INF, NEG_INF, NEG_INF);
        b1 = make_float4(NEG_INF, NEG_INF, NEG_INF, NEG_INF);
    }

    // Column j+4 scalars (first element of neighbor float4) — L1 hits.
    const float* c0f = (const float*)c0;
    const float* c1f = (const float*)c1;
    const size_t fbase = (pos << 2) + 4;   // float index of element j+4, row i
    float a0e = hasCol ? c0f[fbase] : NEG_INF;
    float b0e = hasCol ? c1f[fbase] : NEG_INF;
    float a1e = (hasCol && hasRow) ? c0f[fbase + 512] : NEG_INF;
    float b1e = (hasCol && hasRow) ? c1f[fbase + 512] : NEG_INF;

    float4 o0, o1;
    // out0: own = c0, cross = c1[i,j]
    o0.x = fmax5(a0.x, a0.y, a1.x, a1.y, b0.x);
    o0.y = fmax5(a0.y, a0.z, a1.y, a1.z, b0.y);
    o0.z = fmax5(a0.z, a0.w, a1.z, a1.w, b0.z);
    o0.w = fmax5(a0.w, a0e,  a1.w, a1e,  b0.w);
    // out1: own = c1, cross = c0[i+1,j+1]
    o1.x = fmax5(b0.x, b0.y, b1.x, b1.y, a1.y);
    o1.y = fmax5(b0.y, b0.z, b1.y, b1.z, a1.z);
    o1.z = fmax5(b0.z, b0.w, b1.z, b1.w, a1.w);
    o1.w = fmax5(b0.w, b0e,  b1.w, b1e,  a1e);

    __stcs(&out0[pos], o0);   // streaming store: output never re-read
    __stcs(&out1[pos], o1);
}

extern "C" void kernel_launch(void* const* d_in, const int* in_sizes, int n_in,
                              void* d_out, int out_size) {
    const float4* c0 = (const float4*)d_in[0];
    const float4* c1 = (const float4*)d_in[1];
    float4* out0 = (float4*)d_out;
    float4* out1 = out0 + 8388608;  // B*C*H*W / 4 float4 elements

    const int total = 8388608;      // 128 planes * 512 rows * 128 vec-cols
    const int threads = 256;
    const int blocks = total / threads; // 32768
    lattice_pool_kernel<<<blocks, threads>>>(c0, c1, out0, out1);
}